// round 14
// baseline (speedup 1.0000x reference)
#include <cuda_runtime.h>
#include <cuda_bf16.h>
#include <math.h>
#include <stdint.h>

// Problem constants (fixed by the dataset): B=128, S=1024, d=64, D=64.
#define S_LEN   1024
#define NSTEP   512     // fused pair steps
#define D_DIM   64
#define NSYM    64
#define NPAIR   (NSYM * NSYM)
#define PADROW  72      // smem row stride in bf16 (144B: conflict-free ldmatrix)

// Pair table, bf16, in WARP-CHAIN consumption order:
// pairT[p][j][i] = sum_j' core[s1][i][j']*core[s2][j'][j],  p = s1*64+s2.
// uint4 index = p*512 + piece*32 + (j>>1),  piece = (j&1)*8 + (i>>3)  (0..15),
// u32 sub-index = (i&7)>>1  (bf16x2, even i in low half).
// Consumer: lane l = j>>1 reads 16 chunks (piece 0..15) at stride 32 uint4 —
// every LDG.128 is a coalesced 512B warp transaction.
__device__ __nv_bfloat16 g_pairT[NPAIR * D_DIM * D_DIM];    // 32 MB
// bf16 copies of core: row-major and transposed.
__device__ __nv_bfloat16 g_core_bf [NSYM * D_DIM * D_DIM];  // [s][i][j']
__device__ __nv_bfloat16 g_coreT_bf[NSYM * D_DIM * D_DIM];  // [s][j][j'] = core[s][j'][j]

// reinterpret a u32 as bf16x2 (via union; no pointer aliasing)
__device__ __forceinline__ __nv_bfloat162 u2bf2(unsigned int u) {
    union { unsigned int ui; __nv_bfloat162 b2; } cv;
    cv.ui = u;
    return cv.b2;
}
// pack two f32 into one bf16x2 u32: low 16 = lo (even index), high 16 = hi
__device__ __forceinline__ unsigned int bfpack(float lo, float hi) {
    unsigned int r;
    asm("cvt.rn.satfinite.bf16x2.f32 %0, %1, %2;" : "=r"(r) : "f"(hi), "f"(lo));
    return r;
}
static __device__ __forceinline__ uint32_t smem_u32(const void* p) {
    uint32_t a;
    asm("{ .reg .u64 t; cvta.to.shared.u64 t, %1; cvt.u32.u64 %0, t; }"
        : "=r"(a) : "l"(p));
    return a;
}

// ---------------------------------------------------------------------------
// Prep0: fp32 core -> bf16 row-major + bf16 transposed.
// ---------------------------------------------------------------------------
__global__ void ttrain_cvt_kernel(const float* __restrict__ core) {
    int idx = blockIdx.x * blockDim.x + threadIdx.x;
    if (idx < NSYM * D_DIM * D_DIM) {
        int s   = idx >> 12;
        int rem = idx & 4095;
        int i   = rem >> 6;      // row
        int jp  = rem & 63;      // col
        __nv_bfloat16 v = __float2bfloat16(core[idx]);
        g_core_bf[idx] = v;
        g_coreT_bf[(s << 12) + (jp << 6) + i] = v;
    }
}

// ---------------------------------------------------------------------------
// Prep1: pair-table build on tensor cores via mma.sync.m16n8k16 (bf16, fp32
// accum).  One CTA (4 warps) per pair p = s1*64 + s2.
//   D[j][i] = sum_k A[j][k] * B[i][k],  A = coreT_bf[s2] (M=64, row j),
//   B = core_bf[s1] (N=64, row i), K=64.  Warp w: m-rows [16w, 16w+16).
// Epilogue stores straight into the warp-chain consumption layout.
// ---------------------------------------------------------------------------
__global__ __launch_bounds__(128) void ttrain_pair_mma_kernel() {
    __shared__ __align__(16) __nv_bfloat16 smA[D_DIM * PADROW];
    __shared__ __align__(16) __nv_bfloat16 smB[D_DIM * PADROW];

    const int tid = threadIdx.x;
    const int wid = tid >> 5;
    const int lid = tid & 31;
    const int p   = blockIdx.x;
    const int s1  = p >> 6;
    const int s2  = p & 63;

    // Stage A (transposed s2) and B (s1) into padded smem: 512 chunks of 16B.
    {
        const uint4* Ag = reinterpret_cast<const uint4*>(g_coreT_bf + (s2 << 12));
        const uint4* Bg = reinterpret_cast<const uint4*>(g_core_bf  + (s1 << 12));
        for (int c = tid; c < 512; c += 128) {
            int r  = c >> 3;
            int ch = c & 7;
            *reinterpret_cast<uint4*>(smA + r * PADROW + ch * 8) = Ag[c];
            *reinterpret_cast<uint4*>(smB + r * PADROW + ch * 8) = Bg[c];
        }
    }
    __syncthreads();

    const uint32_t smA_u = smem_u32(smA);
    const uint32_t smB_u = smem_u32(smB);
    const int m0 = wid << 4;                 // this warp's 16 m-rows

    float d[8][4];
#pragma unroll
    for (int n = 0; n < 8; ++n)
#pragma unroll
        for (int q = 0; q < 4; ++q) d[n][q] = 0.f;

#pragma unroll
    for (int k0 = 0; k0 < 64; k0 += 16) {
        uint32_t a0, a1, a2, a3;
        {
            int row  = m0 + (lid & 15);
            int koff = k0 + ((lid >> 4) << 3);
            uint32_t addr = smA_u + (row * PADROW + koff) * 2;
            asm volatile(
                "ldmatrix.sync.aligned.m8n8.x4.shared.b16 {%0,%1,%2,%3}, [%4];"
                : "=r"(a0), "=r"(a1), "=r"(a2), "=r"(a3) : "r"(addr));
        }
#pragma unroll
        for (int nt = 0; nt < 4; ++nt) {
            const int n0 = nt << 4;
            uint32_t b0, b1, b2, b3;
            {
                int row  = n0 + (lid & 7) + ((lid >> 4) << 3);
                int koff = k0 + (((lid >> 3) & 1) << 3);
                uint32_t addr = smB_u + (row * PADROW + koff) * 2;
                asm volatile(
                    "ldmatrix.sync.aligned.m8n8.x4.shared.b16 {%0,%1,%2,%3}, [%4];"
                    : "=r"(b0), "=r"(b1), "=r"(b2), "=r"(b3) : "r"(addr));
            }
            asm volatile(
                "mma.sync.aligned.m16n8k16.row.col.f32.bf16.bf16.f32 "
                "{%0,%1,%2,%3}, {%4,%5,%6,%7}, {%8,%9}, {%0,%1,%2,%3};"
                : "+f"(d[2*nt][0]), "+f"(d[2*nt][1]),
                  "+f"(d[2*nt][2]), "+f"(d[2*nt][3])
                : "r"(a0), "r"(a1), "r"(a2), "r"(a3), "r"(b0), "r"(b1));
            asm volatile(
                "mma.sync.aligned.m16n8k16.row.col.f32.bf16.bf16.f32 "
                "{%0,%1,%2,%3}, {%4,%5,%6,%7}, {%8,%9}, {%0,%1,%2,%3};"
                : "+f"(d[2*nt+1][0]), "+f"(d[2*nt+1][1]),
                  "+f"(d[2*nt+1][2]), "+f"(d[2*nt+1][3])
                : "r"(a0), "r"(a1), "r"(a2), "r"(a3), "r"(b2), "r"(b3));
        }
    }

    // Epilogue: lane l holds rows j_lo = m0+(l>>2), j_hi = j_lo+8;
    // cols i = 8*nt + 2*(l&3) (+1).  Store into warp-chain layout:
    // u32 idx = ((p*512 + ((j&1)*8 + (i>>3))*32 + (j>>1)) << 2) + ((i&7)>>1).
    {
        unsigned int* outw = reinterpret_cast<unsigned int*>(g_pairT);
        const int r    = lid >> 2;
        const int cc   = (lid & 3) << 1;
        const int j_lo = m0 + r;
        const int j_hi = m0 + r + 8;
#pragma unroll
        for (int nt = 0; nt < 8; ++nt) {
            const int i   = (nt << 3) + cc;
            const int sub = (i & 7) >> 1;          // = l&3
            const int idx_lo = (((p << 9) + (((j_lo & 1) << 3) + nt) * 32 +
                                 (j_lo >> 1)) << 2) + sub;
            const int idx_hi = (((p << 9) + (((j_hi & 1) << 3) + nt) * 32 +
                                 (j_hi >> 1)) << 2) + sub;
            outw[idx_lo] = bfpack(d[nt][0], d[nt][1]);
            outw[idx_hi] = bfpack(d[nt][2], d[nt][3]);
        }
    }
}

// ---------------------------------------------------------------------------
// Main chain v4: ONE WARP per chain, one CTA (32 threads) per batch element,
// 512 fused steps.  Lane l owns output rows j = 2l and 2l+1:
//   8 broadcast LDS.128 of the full bf16 c (issued first) +
//   16 coalesced LDG.128 prefetch (distance-1 ring, DEPTH=2) +
//   64 HFMA2 (8 accumulators, 8-deep chains) + hadd2 trees,
//   then ONE bf16x2 STS (both outputs) + __syncwarp.  No barriers, no shfl.
// Renorm each step: exact power-of-two scale from exponent of c[0]
// (cancels exactly in the final log); zero exponent field -> scale 1.
// ---------------------------------------------------------------------------
__global__ __launch_bounds__(32, 1) void ttrain_main_kernel(
    const int*   __restrict__ X,
    const float* __restrict__ lb,
    const float* __restrict__ rb,
    float*       __restrict__ out)
{
    __shared__ __align__(16) unsigned int s_c[2][32];   // bf16x2: c[2l],c[2l+1]
    __shared__ int sP[NSTEP];

    const int l = threadIdx.x;      // 0..31
    const int b = blockIdx.x;

    // Stage fused pair indices: pidx[t] = X[2t]*64 + X[2t+1].
    const int2* Xb2 = reinterpret_cast<const int2*>(X + b * S_LEN);
    for (int k = l; k < NSTEP; k += 32) {
        int2 x2 = Xb2[k];
        sP[k] = (x2.x << 6) | x2.y;
    }
    s_c[0][l] = bfpack(lb[2 * l], lb[2 * l + 1]);
    __syncwarp();

    // My 16 chunks: uint4 idx = p*512 + m*32 + l (m=0..7 row 2l, 8..15 row 2l+1).
    const uint4* wbase = reinterpret_cast<const uint4*>(g_pairT);

    uint4 ring[2][16];
#define LOADW(dst, tt) {                                                   \
        const uint4* pw_ = wbase + (sP[(tt) & (NSTEP - 1)] << 9) + l;      \
        _Pragma("unroll")                                                  \
        for (int m_ = 0; m_ < 16; ++m_) (dst)[m_] = pw_[m_ << 5]; }

    LOADW(ring[0], 0)

    int e_total = 0;

#pragma unroll 2
    for (int t = 0; t < NSTEP; ++t) {
        const int buf = t & 1;

        // Full c vector: 8 broadcast LDS.128 (serial dependency -> first).
        const uint4* cv4 = reinterpret_cast<const uint4*>(&s_c[buf][0]);
        uint4 carr[8];
#pragma unroll
        for (int m = 0; m < 8; ++m) carr[m] = cv4[m];

        // Prefetch step t+1 into the other ring buffer.
        LOADW(ring[buf ^ 1], t + 1)

        // Renorm scale from c[0]'s exponent (low bf16 of carr[0].x).
        int ef = (carr[0].x >> 7) & 0xff;
        int e  = (ef == 0) ? 0 : ef - 127;
        e = e < -96 ? -96 : (e > 96 ? 96 : e);
        e_total += e;
        const float scale = __int_as_float((127 - e) << 23);

        const uint4* wq = ring[buf];

        __nv_bfloat162 A0 = __float2bfloat162_rn(0.f);
        __nv_bfloat162 A1 = __float2bfloat162_rn(0.f);
        __nv_bfloat162 A2 = __float2bfloat162_rn(0.f);
        __nv_bfloat162 A3 = __float2bfloat162_rn(0.f);
        __nv_bfloat162 B0 = __float2bfloat162_rn(0.f);
        __nv_bfloat162 B1 = __float2bfloat162_rn(0.f);
        __nv_bfloat162 B2 = __float2bfloat162_rn(0.f);
        __nv_bfloat162 B3 = __float2bfloat162_rn(0.f);
#pragma unroll
        for (int m = 0; m < 8; ++m) {
            __nv_bfloat162 cx = u2bf2(carr[m].x), cy = u2bf2(carr[m].y);
            __nv_bfloat162 cz = u2bf2(carr[m].z), cw = u2bf2(carr[m].w);
            A0 = __hfma2(cx, u2bf2(wq[m].x), A0);
            A1 = __hfma2(cy, u2bf2(wq[m].y), A1);
            A2 = __hfma2(cz, u2bf2(wq[m].z), A2);
            A3 = __hfma2(cw, u2bf2(wq[m].w), A3);
            B0 = __hfma2(cx, u2bf2(wq[m + 8].x), B0);
            B1 = __hfma2(cy, u2bf2(wq[m + 8].y), B1);
            B2 = __hfma2(cz, u2bf2(wq[m + 8].z), B2);
            B3 = __hfma2(cw, u2bf2(wq[m + 8].w), B3);
        }
        __nv_bfloat162 sa = __hadd2(__hadd2(A0, A1), __hadd2(A2, A3));
        __nv_bfloat162 sb = __hadd2(__hadd2(B0, B1), __hadd2(B2, B3));
        float ta = __bfloat162float(__low2bfloat16(sa)) +
                   __bfloat162float(__high2bfloat16(sa));
        float tb = __bfloat162float(__low2bfloat16(sb)) +
                   __bfloat162float(__high2bfloat16(sb));

        s_c[buf ^ 1][l] = bfpack(ta * scale, tb * scale);
        __syncwarp();
    }
#undef LOADW

    // Final contraction with right boundary + log-likelihood.
    // After 512 steps the live buffer is s_c[0].
    unsigned int cf = s_c[0][l];
    float v = __bfloat162float(__low2bfloat16(u2bf2(cf)))  * rb[2 * l] +
              __bfloat162float(__high2bfloat16(u2bf2(cf))) * rb[2 * l + 1];
#pragma unroll
    for (int o = 16; o >= 1; o >>= 1)
        v += __shfl_xor_sync(0xffffffffu, v, o);
    if (l == 0) {
        out[b] = (float)(2.0 * ((double)e_total * 0.6931471805599453 +
                                log(fabs((double)v))));
    }
}

extern "C" void kernel_launch(void* const* d_in, const int* in_sizes, int n_in,
                              void* d_out, int out_size) {
    // metadata order: X [128*1024] i32, core [64*64*64] f32,
    //                 left_boundary [64] f32, right_boundary [64] f32
    const int*   X    = (const int*)  d_in[0];
    const float* core = (const float*)d_in[1];
    const float* lb   = (const float*)d_in[2];
    const float* rb   = (const float*)d_in[3];
    float*       out  = (float*)d_out;

    ttrain_cvt_kernel<<<(NSYM * D_DIM * D_DIM + 255) / 256, 256>>>(core);
    ttrain_pair_mma_kernel<<<NPAIR, 128>>>();
    ttrain_main_kernel<<<128, 32>>>(X, lb, rb, out);
}

// round 15
// speedup vs baseline: 1.0428x; 1.0428x over previous
#include <cuda_runtime.h>
#include <cuda_bf16.h>
#include <math.h>
#include <stdint.h>

// Problem constants (fixed by the dataset): B=128, S=1024, d=64, D=64.
#define S_LEN   1024
#define NSTEP   512     // fused pair steps; ring depth must divide NSTEP
#define D_DIM   64
#define NSYM    64
#define NPAIR   (NSYM * NSYM)
#define DEPTH   4       // ring buffers; prefetch distance 3; 512 % 4 == 0
#define PADROW  72      // smem row stride in bf16 (144B: conflict-free ldmatrix)

// Pair table, bf16, in R8/R12 consumption order (4-warp main kernel):
// uint4 index = p*512 + (j>>4)*128 + m*32 + (j&15)*2 + pp, holding elements
// i = pp*32+8m .. +8 of pairT[p][j][i] = sum_j' core[s1][i][j']*core[s2][j'][j].
__device__ __nv_bfloat16 g_pairT[NPAIR * D_DIM * D_DIM];    // 32 MB
// bf16 copies of core: row-major and transposed.
__device__ __nv_bfloat16 g_core_bf [NSYM * D_DIM * D_DIM];  // [s][i][j']
__device__ __nv_bfloat16 g_coreT_bf[NSYM * D_DIM * D_DIM];  // [s][j][j'] = core[s][j'][j]

// reinterpret a u32 as bf16x2 (via union; no pointer aliasing)
__device__ __forceinline__ __nv_bfloat162 u2bf2(unsigned int u) {
    union { unsigned int ui; __nv_bfloat162 b2; } cv;
    cv.ui = u;
    return cv.b2;
}
// pack two f32 into one bf16x2 u32: low 16 = lo (even index), high 16 = hi
__device__ __forceinline__ unsigned int bfpack(float lo, float hi) {
    unsigned int r;
    asm("cvt.rn.satfinite.bf16x2.f32 %0, %1, %2;" : "=r"(r) : "f"(hi), "f"(lo));
    return r;
}
static __device__ __forceinline__ uint32_t smem_u32(const void* p) {
    uint32_t a;
    asm("{ .reg .u64 t; cvta.to.shared.u64 t, %1; cvt.u32.u64 %0, t; }"
        : "=r"(a) : "l"(p));
    return a;
}

// ---------------------------------------------------------------------------
// Prep0: fp32 core -> bf16 row-major + bf16 transposed.
// ---------------------------------------------------------------------------
__global__ void ttrain_cvt_kernel(const float* __restrict__ core) {
    int idx = blockIdx.x * blockDim.x + threadIdx.x;
    if (idx < NSYM * D_DIM * D_DIM) {
        int s   = idx >> 12;
        int rem = idx & 4095;
        int i   = rem >> 6;      // row
        int jp  = rem & 63;      // col
        __nv_bfloat16 v = __float2bfloat16(core[idx]);
        g_core_bf[idx] = v;
        g_coreT_bf[(s << 12) + (jp << 6) + i] = v;
    }
}

// ---------------------------------------------------------------------------
// Prep1: pair-table build on tensor cores via mma.sync.m16n8k16 (bf16, fp32
// accum).  One CTA (4 warps) per pair p = s1*64 + s2.
//   D[j][i] = sum_k A[j][k] * B[i][k],  A = coreT_bf[s2] (M=64, row j),
//   B = core_bf[s1] (N=64, row i), K=64.  Warp w: m-rows [16w, 16w+16).
// Epilogue stores straight into the R8/R12 consumption layout.
// (Identical to the passing R12 kernel.)
// ---------------------------------------------------------------------------
__global__ __launch_bounds__(128) void ttrain_pair_mma_kernel() {
    __shared__ __align__(16) __nv_bfloat16 smA[D_DIM * PADROW];
    __shared__ __align__(16) __nv_bfloat16 smB[D_DIM * PADROW];

    const int tid = threadIdx.x;
    const int wid = tid >> 5;
    const int lid = tid & 31;
    const int p   = blockIdx.x;
    const int s1  = p >> 6;
    const int s2  = p & 63;

    {
        const uint4* Ag = reinterpret_cast<const uint4*>(g_coreT_bf + (s2 << 12));
        const uint4* Bg = reinterpret_cast<const uint4*>(g_core_bf  + (s1 << 12));
        for (int c = tid; c < 512; c += 128) {
            int r  = c >> 3;
            int ch = c & 7;
            *reinterpret_cast<uint4*>(smA + r * PADROW + ch * 8) = Ag[c];
            *reinterpret_cast<uint4*>(smB + r * PADROW + ch * 8) = Bg[c];
        }
    }
    __syncthreads();

    const uint32_t smA_u = smem_u32(smA);
    const uint32_t smB_u = smem_u32(smB);
    const int m0 = wid << 4;

    float d[8][4];
#pragma unroll
    for (int n = 0; n < 8; ++n)
#pragma unroll
        for (int q = 0; q < 4; ++q) d[n][q] = 0.f;

#pragma unroll
    for (int k0 = 0; k0 < 64; k0 += 16) {
        uint32_t a0, a1, a2, a3;
        {
            int row  = m0 + (lid & 15);
            int koff = k0 + ((lid >> 4) << 3);
            uint32_t addr = smA_u + (row * PADROW + koff) * 2;
            asm volatile(
                "ldmatrix.sync.aligned.m8n8.x4.shared.b16 {%0,%1,%2,%3}, [%4];"
                : "=r"(a0), "=r"(a1), "=r"(a2), "=r"(a3) : "r"(addr));
        }
#pragma unroll
        for (int nt = 0; nt < 4; ++nt) {
            const int n0 = nt << 4;
            uint32_t b0, b1, b2, b3;
            {
                int row  = n0 + (lid & 7) + ((lid >> 4) << 3);
                int koff = k0 + (((lid >> 3) & 1) << 3);
                uint32_t addr = smB_u + (row * PADROW + koff) * 2;
                asm volatile(
                    "ldmatrix.sync.aligned.m8n8.x4.shared.b16 {%0,%1,%2,%3}, [%4];"
                    : "=r"(b0), "=r"(b1), "=r"(b2), "=r"(b3) : "r"(addr));
            }
            asm volatile(
                "mma.sync.aligned.m16n8k16.row.col.f32.bf16.bf16.f32 "
                "{%0,%1,%2,%3}, {%4,%5,%6,%7}, {%8,%9}, {%0,%1,%2,%3};"
                : "+f"(d[2*nt][0]), "+f"(d[2*nt][1]),
                  "+f"(d[2*nt][2]), "+f"(d[2*nt][3])
                : "r"(a0), "r"(a1), "r"(a2), "r"(a3), "r"(b0), "r"(b1));
            asm volatile(
                "mma.sync.aligned.m16n8k16.row.col.f32.bf16.bf16.f32 "
                "{%0,%1,%2,%3}, {%4,%5,%6,%7}, {%8,%9}, {%0,%1,%2,%3};"
                : "+f"(d[2*nt+1][0]), "+f"(d[2*nt+1][1]),
                  "+f"(d[2*nt+1][2]), "+f"(d[2*nt+1][3])
                : "r"(a0), "r"(a1), "r"(a2), "r"(a3), "r"(b2), "r"(b3));
        }
    }

    {
        unsigned int* outw = reinterpret_cast<unsigned int*>(g_pairT);
        const int r  = lid >> 2;
        const int cc = (lid & 3) << 1;
        const int j_lo = m0 + r;
        const int j_hi = m0 + r + 8;
#pragma unroll
        for (int nt = 0; nt < 8; ++nt) {
            const int i = (nt << 3) + cc;
            const int common = (p << 9) + (((i & 31) >> 3) << 5) + (i >> 5);
            const int idx_lo = ((common + ((j_lo >> 4) << 7) +
                                 ((j_lo & 15) << 1)) << 2) + ((i & 7) >> 1);
            const int idx_hi = ((common + ((j_hi >> 4) << 7) +
                                 ((j_hi & 15) << 1)) << 2) + ((i & 7) >> 1);
            outw[idx_lo] = bfpack(d[nt][0], d[nt][1]);
            outw[idx_hi] = bfpack(d[nt][2], d[nt][3]);
        }
    }
}

// ---------------------------------------------------------------------------
// Main chain v5: TWO chains interleaved on the SAME 4 warps.  One CTA (128
// threads) handles batches 2b and 2b+1; each step body runs chain-A then
// chain-B (independent register dependency chains -> the scheduler fills A's
// stalls with B's issue), and ONE __syncthreads serves both chain-steps.
// Per-chain datapath is bit-identical to the proven R12 kernel: warp w owns
// outputs j in [16w,16w+16); lane l: j = 16w + (l>>1), pp = l&1; 4 broadcast
// LDS.128 of c + 4 coalesced LDG.128 prefetch (distance-3 ring) + 16 HFMA2,
// shfl pair-combine, bf16 store.  Renorm each step: exact power-of-two scale
// from the exponent of c[0] (cancels exactly in the final log).
// ---------------------------------------------------------------------------
__global__ __launch_bounds__(128, 1) void ttrain_main_kernel(
    const int*   __restrict__ X,
    const float* __restrict__ lb,
    const float* __restrict__ rb,
    float*       __restrict__ out)
{
    __shared__ __align__(16) unsigned short s_c[2][2][D_DIM]; // [chain][buf][j]
    __shared__ float s_red[2][4];
    __shared__ int   sP[2][NSTEP];

    const int tid = threadIdx.x;
    const int w   = tid >> 5;
    const int l   = tid & 31;
    const int pp  = l & 1;
    const int b0  = blockIdx.x << 1;

    // Stage fused pair indices for both chains.
    {
        const int2* Xa = reinterpret_cast<const int2*>(X + b0 * S_LEN);
        const int2* Xb = reinterpret_cast<const int2*>(X + (b0 + 1) * S_LEN);
        for (int k = tid; k < NSTEP; k += 128) {
            int2 xa = Xa[k];
            int2 xb = Xb[k];
            sP[0][k] = (xa.x << 6) | xa.y;
            sP[1][k] = (xb.x << 6) | xb.y;
        }
    }
    if (tid < D_DIM) {
        unsigned short v = __bfloat16_as_ushort(__float2bfloat16(lb[tid]));
        s_c[0][0][tid] = v;
        s_c[1][0][tid] = v;
    }
    __syncthreads();

    const uint4* wbase = reinterpret_cast<const uint4*>(g_pairT);
    const int    toff  = (w << 7) + l;

    uint4 ring0[DEPTH][4], ring1[DEPTH][4];
#define LOADW(dst, ch, tt) {                                                 \
        const uint4* pw_ = wbase + (sP[ch][(tt) & (NSTEP - 1)] << 9) + toff; \
        (dst)[0] = pw_[0];  (dst)[1] = pw_[32];                              \
        (dst)[2] = pw_[64]; (dst)[3] = pw_[96]; }

    LOADW(ring0[0], 0, 0) LOADW(ring0[1], 0, 1) LOADW(ring0[2], 0, 2)
    LOADW(ring1[0], 1, 0) LOADW(ring1[1], 1, 1) LOADW(ring1[2], 1, 2)

    int e_tot0 = 0, e_tot1 = 0;

    for (int t0 = 0; t0 < NSTEP; t0 += DEPTH) {
#pragma unroll
        for (int u = 0; u < DEPTH; ++u) {
            const int t   = t0 + u;
            const int buf = t & 1;

            // Serial-dependency loads for BOTH chains first.
            unsigned short c0a = s_c[0][buf][0];
            unsigned short c0b = s_c[1][buf][0];
            const uint4* ca4 =
                reinterpret_cast<const uint4*>(&s_c[0][buf][pp << 5]);
            const uint4* cb4 =
                reinterpret_cast<const uint4*>(&s_c[1][buf][pp << 5]);
            uint4 carrA[4], carrB[4];
#pragma unroll
            for (int m = 0; m < 4; ++m) { carrA[m] = ca4[m]; carrB[m] = cb4[m]; }

            // Prefetch step t+3 for both chains (off the critical path).
            LOADW(ring0[(u + DEPTH - 1) % DEPTH], 0, t + DEPTH - 1)
            LOADW(ring1[(u + DEPTH - 1) % DEPTH], 1, t + DEPTH - 1)

            // Renorm scales.
            int efa = (c0a >> 7) & 0xff;
            int ea  = (efa == 0) ? 0 : efa - 127;
            ea = ea < -96 ? -96 : (ea > 96 ? 96 : ea);
            e_tot0 += ea;
            const float scaleA = __int_as_float((127 - ea) << 23);
            int efb = (c0b >> 7) & 0xff;
            int eb  = (efb == 0) ? 0 : efb - 127;
            eb = eb < -96 ? -96 : (eb > 96 ? 96 : eb);
            e_tot1 += eb;
            const float scaleB = __int_as_float((127 - eb) << 23);

            const uint4* wqA = ring0[u];
            const uint4* wqB = ring1[u];

            // Chain A and chain B MACs: independent chains, scheduler overlaps.
            __nv_bfloat162 A0 = __float2bfloat162_rn(0.f), A1 = A0,
                           A2 = A0, A3 = A0;
            __nv_bfloat162 Bb0 = A0, Bb1 = A0, Bb2 = A0, Bb3 = A0;
#pragma unroll
            for (int m = 0; m < 4; ++m) {
                A0  = __hfma2(u2bf2(carrA[m].x), u2bf2(wqA[m].x), A0);
                Bb0 = __hfma2(u2bf2(carrB[m].x), u2bf2(wqB[m].x), Bb0);
                A1  = __hfma2(u2bf2(carrA[m].y), u2bf2(wqA[m].y), A1);
                Bb1 = __hfma2(u2bf2(carrB[m].y), u2bf2(wqB[m].y), Bb1);
                A2  = __hfma2(u2bf2(carrA[m].z), u2bf2(wqA[m].z), A2);
                Bb2 = __hfma2(u2bf2(carrB[m].z), u2bf2(wqB[m].z), Bb2);
                A3  = __hfma2(u2bf2(carrA[m].w), u2bf2(wqA[m].w), A3);
                Bb3 = __hfma2(u2bf2(carrB[m].w), u2bf2(wqB[m].w), Bb3);
            }
            __nv_bfloat162 sa = __hadd2(__hadd2(A0, A1), __hadd2(A2, A3));
            __nv_bfloat162 sb = __hadd2(__hadd2(Bb0, Bb1), __hadd2(Bb2, Bb3));
            float totA = __bfloat162float(__low2bfloat16(sa)) +
                         __bfloat162float(__high2bfloat16(sa));
            float totB = __bfloat162float(__low2bfloat16(sb)) +
                         __bfloat162float(__high2bfloat16(sb));
            totA += __shfl_xor_sync(0xffffffffu, totA, 1);
            totB += __shfl_xor_sync(0xffffffffu, totB, 1);

            if (pp == 0) {
                const int jdst = (w << 4) + (l >> 1);
                s_c[0][buf ^ 1][jdst] =
                    __bfloat16_as_ushort(__float2bfloat16(totA * scaleA));
                s_c[1][buf ^ 1][jdst] =
                    __bfloat16_as_ushort(__float2bfloat16(totB * scaleB));
            }
            __syncthreads();
        }
    }
#undef LOADW

    // Final contraction with right boundary + log-likelihood, both chains.
    float v0 = 0.f, v1 = 0.f;
    if (tid < D_DIM) {
        float r = rb[tid];
        v0 = __bfloat162float(__ushort_as_bfloat16(s_c[0][0][tid])) * r;
        v1 = __bfloat162float(__ushort_as_bfloat16(s_c[1][0][tid])) * r;
    }
#pragma unroll
    for (int o = 16; o >= 1; o >>= 1) {
        v0 += __shfl_xor_sync(0xffffffffu, v0, o);
        v1 += __shfl_xor_sync(0xffffffffu, v1, o);
    }
    if (l == 0) { s_red[0][w] = v0; s_red[1][w] = v1; }
    __syncthreads();
    if (tid == 0) {
        double ov0 = (double)s_red[0][0] + (double)s_red[0][1] +
                     (double)s_red[0][2] + (double)s_red[0][3];
        double ov1 = (double)s_red[1][0] + (double)s_red[1][1] +
                     (double)s_red[1][2] + (double)s_red[1][3];
        out[b0]     = (float)(2.0 * ((double)e_tot0 * 0.6931471805599453 +
                                     log(fabs(ov0))));
        out[b0 + 1] = (float)(2.0 * ((double)e_tot1 * 0.6931471805599453 +
                                     log(fabs(ov1))));
    }
}

extern "C" void kernel_launch(void* const* d_in, const int* in_sizes, int n_in,
                              void* d_out, int out_size) {
    // metadata order: X [128*1024] i32, core [64*64*64] f32,
    //                 left_boundary [64] f32, right_boundary [64] f32
    const int*   X    = (const int*)  d_in[0];
    const float* core = (const float*)d_in[1];
    const float* lb   = (const float*)d_in[2];
    const float* rb   = (const float*)d_in[3];
    float*       out  = (float*)d_out;

    ttrain_cvt_kernel<<<(NSYM * D_DIM * D_DIM + 255) / 256, 256>>>(core);
    ttrain_pair_mma_kernel<<<NPAIR, 128>>>();
    ttrain_main_kernel<<<64, 128>>>(X, lb, rb, out);
}

// round 16
// speedup vs baseline: 1.3149x; 1.2609x over previous
#include <cuda_runtime.h>
#include <cuda_bf16.h>
#include <math.h>
#include <stdint.h>

// Problem constants (fixed by the dataset): B=128, S=1024, d=64, D=64.
#define S_LEN   1024
#define NSTEP   512     // fused pair steps; ring depth must divide NSTEP
#define D_DIM   64
#define NSYM    64
#define NPAIR   (NSYM * NSYM)
#define DEPTH   4       // ring buffers; prefetch distance 3; 512 % 4 == 0
#define PADROW  72      // smem row stride in bf16 (144B: conflict-free ldmatrix)

// Pair table, bf16, in R8/R12 consumption order (4-warp main kernel):
// uint4 index = p*512 + (j>>4)*128 + m*32 + (j&15)*2 + pp, holding elements
// i = pp*32+8m .. +8 of pairT[p][j][i] = sum_j' core[s1][i][j']*core[s2][j'][j].
__device__ __nv_bfloat16 g_pairT[NPAIR * D_DIM * D_DIM];    // 32 MB
// bf16 copies of core: row-major and transposed.
__device__ __nv_bfloat16 g_core_bf [NSYM * D_DIM * D_DIM];  // [s][i][j']
__device__ __nv_bfloat16 g_coreT_bf[NSYM * D_DIM * D_DIM];  // [s][j][j'] = core[s][j'][j]

// reinterpret a u32 as bf16x2 (via union; no pointer aliasing)
__device__ __forceinline__ __nv_bfloat162 u2bf2(unsigned int u) {
    union { unsigned int ui; __nv_bfloat162 b2; } cv;
    cv.ui = u;
    return cv.b2;
}
// pack two f32 into one bf16x2 u32: low 16 = lo (even index), high 16 = hi
__device__ __forceinline__ unsigned int bfpack(float lo, float hi) {
    unsigned int r;
    asm("cvt.rn.satfinite.bf16x2.f32 %0, %1, %2;" : "=r"(r) : "f"(hi), "f"(lo));
    return r;
}
static __device__ __forceinline__ uint32_t smem_u32(const void* p) {
    uint32_t a;
    asm("{ .reg .u64 t; cvta.to.shared.u64 t, %1; cvt.u32.u64 %0, t; }"
        : "=r"(a) : "l"(p));
    return a;
}

// ---------------------------------------------------------------------------
// Prep0: fp32 core -> bf16 row-major + bf16 transposed.  float4-vectorized.
// ---------------------------------------------------------------------------
__global__ void ttrain_cvt_kernel(const float* __restrict__ core) {
    int idx4 = blockIdx.x * blockDim.x + threadIdx.x;   // 65536 float4 chunks
    if (idx4 < (NSYM * D_DIM * D_DIM) / 4) {
        float4 v = reinterpret_cast<const float4*>(core)[idx4];
        // row-major bf16
        unsigned int* dst = reinterpret_cast<unsigned int*>(g_core_bf);
        dst[idx4 * 2 + 0] = bfpack(v.x, v.y);
        dst[idx4 * 2 + 1] = bfpack(v.z, v.w);
        // transposed bf16 (4 scattered u16 stores)
        int base = idx4 << 2;
        int s  = base >> 12;
        int rem = base & 4095;
        int i  = rem >> 6;       // row
        int j0 = rem & 63;       // first col of the 4
        unsigned short* T = reinterpret_cast<unsigned short*>(g_coreT_bf);
        T[(s << 12) + ((j0 + 0) << 6) + i] = __bfloat16_as_ushort(__float2bfloat16(v.x));
        T[(s << 12) + ((j0 + 1) << 6) + i] = __bfloat16_as_ushort(__float2bfloat16(v.y));
        T[(s << 12) + ((j0 + 2) << 6) + i] = __bfloat16_as_ushort(__float2bfloat16(v.z));
        T[(s << 12) + ((j0 + 3) << 6) + i] = __bfloat16_as_ushort(__float2bfloat16(v.w));
    }
}

// ---------------------------------------------------------------------------
// Prep1: pair-table build on tensor cores via mma.sync.m16n8k16 (bf16, fp32
// accum).  One CTA (4 warps) per pair p = s1*64 + s2.  Identical to the
// passing R12 kernel.
// ---------------------------------------------------------------------------
__global__ __launch_bounds__(128) void ttrain_pair_mma_kernel() {
    __shared__ __align__(16) __nv_bfloat16 smA[D_DIM * PADROW];
    __shared__ __align__(16) __nv_bfloat16 smB[D_DIM * PADROW];

    const int tid = threadIdx.x;
    const int wid = tid >> 5;
    const int lid = tid & 31;
    const int p   = blockIdx.x;
    const int s1  = p >> 6;
    const int s2  = p & 63;

    {
        const uint4* Ag = reinterpret_cast<const uint4*>(g_coreT_bf + (s2 << 12));
        const uint4* Bg = reinterpret_cast<const uint4*>(g_core_bf  + (s1 << 12));
        for (int c = tid; c < 512; c += 128) {
            int r  = c >> 3;
            int ch = c & 7;
            *reinterpret_cast<uint4*>(smA + r * PADROW + ch * 8) = Ag[c];
            *reinterpret_cast<uint4*>(smB + r * PADROW + ch * 8) = Bg[c];
        }
    }
    __syncthreads();

    const uint32_t smA_u = smem_u32(smA);
    const uint32_t smB_u = smem_u32(smB);
    const int m0 = wid << 4;

    float d[8][4];
#pragma unroll
    for (int n = 0; n < 8; ++n)
#pragma unroll
        for (int q = 0; q < 4; ++q) d[n][q] = 0.f;

#pragma unroll
    for (int k0 = 0; k0 < 64; k0 += 16) {
        uint32_t a0, a1, a2, a3;
        {
            int row  = m0 + (lid & 15);
            int koff = k0 + ((lid >> 4) << 3);
            uint32_t addr = smA_u + (row * PADROW + koff) * 2;
            asm volatile(
                "ldmatrix.sync.aligned.m8n8.x4.shared.b16 {%0,%1,%2,%3}, [%4];"
                : "=r"(a0), "=r"(a1), "=r"(a2), "=r"(a3) : "r"(addr));
        }
#pragma unroll
        for (int nt = 0; nt < 4; ++nt) {
            const int n0 = nt << 4;
            uint32_t b0, b1, b2, b3;
            {
                int row  = n0 + (lid & 7) + ((lid >> 4) << 3);
                int koff = k0 + (((lid >> 3) & 1) << 3);
                uint32_t addr = smB_u + (row * PADROW + koff) * 2;
                asm volatile(
                    "ldmatrix.sync.aligned.m8n8.x4.shared.b16 {%0,%1,%2,%3}, [%4];"
                    : "=r"(b0), "=r"(b1), "=r"(b2), "=r"(b3) : "r"(addr));
            }
            asm volatile(
                "mma.sync.aligned.m16n8k16.row.col.f32.bf16.bf16.f32 "
                "{%0,%1,%2,%3}, {%4,%5,%6,%7}, {%8,%9}, {%0,%1,%2,%3};"
                : "+f"(d[2*nt][0]), "+f"(d[2*nt][1]),
                  "+f"(d[2*nt][2]), "+f"(d[2*nt][3])
                : "r"(a0), "r"(a1), "r"(a2), "r"(a3), "r"(b0), "r"(b1));
            asm volatile(
                "mma.sync.aligned.m16n8k16.row.col.f32.bf16.bf16.f32 "
                "{%0,%1,%2,%3}, {%4,%5,%6,%7}, {%8,%9}, {%0,%1,%2,%3};"
                : "+f"(d[2*nt+1][0]), "+f"(d[2*nt+1][1]),
                  "+f"(d[2*nt+1][2]), "+f"(d[2*nt+1][3])
                : "r"(a0), "r"(a1), "r"(a2), "r"(a3), "r"(b2), "r"(b3));
        }
    }

    {
        unsigned int* outw = reinterpret_cast<unsigned int*>(g_pairT);
        const int r  = lid >> 2;
        const int cc = (lid & 3) << 1;
        const int j_lo = m0 + r;
        const int j_hi = m0 + r + 8;
#pragma unroll
        for (int nt = 0; nt < 8; ++nt) {
            const int i = (nt << 3) + cc;
            const int common = (p << 9) + (((i & 31) >> 3) << 5) + (i >> 5);
            const int idx_lo = ((common + ((j_lo >> 4) << 7) +
                                 ((j_lo & 15) << 1)) << 2) + ((i & 7) >> 1);
            const int idx_hi = ((common + ((j_hi >> 4) << 7) +
                                 ((j_hi & 15) << 1)) << 2) + ((i & 7) >> 1);
            outw[idx_lo] = bfpack(d[nt][0], d[nt][1]);
            outw[idx_hi] = bfpack(d[nt][2], d[nt][3]);
        }
    }
}

// ---------------------------------------------------------------------------
// Main chain v6: R12 shape (1 chain, 4 warps) with a shortened serial step.
// warp w owns outputs j in [16w,16w+16); lane l: j = 16w + (l>>1), pp = l&1.
// DEFERRED PAIR-COMBINE: each thread stores its bf16 PARTIAL (i-half tree
// sum x scale) to s_p[buf^1][pp][j]; the consumer adds the two halves next
// step with HADD2s folded into its load phase.  No shfl, no f32 tail.
// Prefetch LDGs are issued AFTER the MAC tree (inside the STS/BAR shadow).
// Renorm each step: exact power-of-two scale from the exponent of
// c[0] = half0[0]+half1[0] (bf16-exact scale; cancels in the final log).
// ---------------------------------------------------------------------------
__global__ __launch_bounds__(128, 1) void ttrain_main_kernel(
    const int*   __restrict__ X,
    const float* __restrict__ lb,
    const float* __restrict__ rb,
    float*       __restrict__ out)
{
    __shared__ __align__(16) unsigned short s_p[2][2][D_DIM]; // [buf][half][j]
    __shared__ float s_red[4];
    __shared__ int   sP[NSTEP];

    const int tid = threadIdx.x;
    const int b   = blockIdx.x;
    const int w   = tid >> 5;
    const int l   = tid & 31;
    const int pp  = l & 1;

    const int2* Xb2 = reinterpret_cast<const int2*>(X + b * S_LEN);
    for (int k = tid; k < NSTEP; k += 128) {
        int2 x2 = Xb2[k];
        sP[k] = (x2.x << 6) | x2.y;
    }
    if (tid < D_DIM) {
        s_p[0][0][tid] = __bfloat16_as_ushort(__float2bfloat16(lb[tid]));
        s_p[0][1][tid] = 0;                      // bf16 +0
    }
    __syncthreads();

    const uint4* wbase = reinterpret_cast<const uint4*>(g_pairT);
    const int    toff  = (w << 7) + l;

    uint4 ring[DEPTH][4];
#define LOADW(dst, tt) {                                                   \
        const uint4* pw_ = wbase + (sP[(tt) & (NSTEP - 1)] << 9) + toff;   \
        (dst)[0] = pw_[0];  (dst)[1] = pw_[32];                            \
        (dst)[2] = pw_[64]; (dst)[3] = pw_[96]; }

    LOADW(ring[0], 0)
    LOADW(ring[1], 1)
    LOADW(ring[2], 2)

    int e_total = 0;

    for (int t0 = 0; t0 < NSTEP; t0 += DEPTH) {
#pragma unroll
        for (int u = 0; u < DEPTH; ++u) {
            const int t   = t0 + u;
            const int buf = t & 1;

            // --- serial loads first: my c range, both halves ---
            const uint4* h0 =
                reinterpret_cast<const uint4*>(&s_p[buf][0][pp << 5]);
            const uint4* h1 =
                reinterpret_cast<const uint4*>(&s_p[buf][1][pp << 5]);
            uint4 ca[4], cb[4];
#pragma unroll
            for (int m = 0; m < 4; ++m) { ca[m] = h0[m]; cb[m] = h1[m]; }
            unsigned short c0a = s_p[buf][0][0];
            unsigned short c0h = s_p[buf][1][0];

            // Renorm scale (off the MAC dependency chain).
            float c0f = __bfloat162float(__ushort_as_bfloat16(c0a)) +
                        __bfloat162float(__ushort_as_bfloat16(c0h));
            int ef = (__float_as_int(c0f) >> 23) & 0xff;
            int e  = (ef == 0) ? 0 : ef - 127;
            e = e < -96 ? -96 : (e > 96 ? 96 : e);
            e_total += e;
            const __nv_bfloat16 scale_b =
                __ushort_as_bfloat16((unsigned short)((127 - e) << 7));

            const uint4* wq = ring[u];

            // MAC: combine halves (HADD2) feeding HFMA2 chains.
            __nv_bfloat162 A0 = __float2bfloat162_rn(0.f), A1 = A0,
                           A2 = A0, A3 = A0;
#pragma unroll
            for (int m = 0; m < 4; ++m) {
                __nv_bfloat162 cx = __hadd2(u2bf2(ca[m].x), u2bf2(cb[m].x));
                __nv_bfloat162 cy = __hadd2(u2bf2(ca[m].y), u2bf2(cb[m].y));
                __nv_bfloat162 cz = __hadd2(u2bf2(ca[m].z), u2bf2(cb[m].z));
                __nv_bfloat162 cw = __hadd2(u2bf2(ca[m].w), u2bf2(cb[m].w));
                A0 = __hfma2(cx, u2bf2(wq[m].x), A0);
                A1 = __hfma2(cy, u2bf2(wq[m].y), A1);
                A2 = __hfma2(cz, u2bf2(wq[m].z), A2);
                A3 = __hfma2(cw, u2bf2(wq[m].w), A3);
            }
            __nv_bfloat162 st = __hadd2(__hadd2(A0, A1), __hadd2(A2, A3));
            __nv_bfloat16 part = __hmul(
                __hadd(__low2bfloat16(st), __high2bfloat16(st)), scale_b);

            // Prefetch step t+3 (issued in the STS/BAR shadow).
            LOADW(ring[(u + DEPTH - 1) % DEPTH], t + DEPTH - 1)

            // Store my bf16 partial: half pp, row j.
            s_p[buf ^ 1][pp][(w << 4) + (l >> 1)] =
                __bfloat16_as_ushort(part);
            __syncthreads();
        }
    }
#undef LOADW

    // Final contraction with right boundary + log-likelihood.
    float v = 0.f;
    if (tid < D_DIM) {
        v = (__bfloat162float(__ushort_as_bfloat16(s_p[0][0][tid])) +
             __bfloat162float(__ushort_as_bfloat16(s_p[0][1][tid]))) * rb[tid];
    }
#pragma unroll
    for (int o = 16; o >= 1; o >>= 1)
        v += __shfl_xor_sync(0xffffffffu, v, o);
    if (l == 0) s_red[w] = v;
    __syncthreads();
    if (tid == 0) {
        double ov = (double)s_red[0] + (double)s_red[1] +
                    (double)s_red[2] + (double)s_red[3];
        out[b] = (float)(2.0 * ((double)e_total * 0.6931471805599453 +
                                log(fabs(ov))));
    }
}

extern "C" void kernel_launch(void* const* d_in, const int* in_sizes, int n_in,
                              void* d_out, int out_size) {
    // metadata order: X [128*1024] i32, core [64*64*64] f32,
    //                 left_boundary [64] f32, right_boundary [64] f32
    const int*   X    = (const int*)  d_in[0];
    const float* core = (const float*)d_in[1];
    const float* lb   = (const float*)d_in[2];
    const float* rb   = (const float*)d_in[3];
    float*       out  = (float*)d_out;

    ttrain_cvt_kernel<<<(NSYM * D_DIM * D_DIM / 4 + 255) / 256, 256>>>(core);
    ttrain_pair_mma_kernel<<<NPAIR, 128>>>();
    ttrain_main_kernel<<<128, 128>>>(X, lb, rb, out);
}